// round 10
// baseline (speedup 1.0000x reference)
#include <cuda_runtime.h>
#include <cstdint>

// ---------------------------------------------------------------------------
// MPNN layer, algebraically decomposed + K-packed f32x2 GEMM loops:
//   K0: zero aggr/cnt
//   Kpre: U = x@(W1a-W1b)+b1, V = x@W1b
//   Kedge: hidden = relu(U[i]+V[j]+relpos@W1p); msg = hidden@W2+b2
//          (phase2 packs K-pairs in f32x2 halves: no per-FMA broadcast mov);
//          scalar atomicAdd scatter (R5/R9-proven construct set)
//   Knode: mean + MLP, both GEMMs K-packed
// ---------------------------------------------------------------------------

#define MAXN 65536
__device__ float g_aggr[MAXN * 64];
__device__ float g_cnt[MAXN];
__device__ float g_u[MAXN * 128];
__device__ float g_v[MAXN * 128];

typedef unsigned long long ull;

__device__ __forceinline__ ull pk2(float a, float b) {
    ull r; asm("mov.b64 %0, {%1, %2};" : "=l"(r) : "f"(a), "f"(b)); return r;
}
__device__ __forceinline__ float2 upk2(ull v) {
    float2 r; asm("mov.b64 {%0, %1}, %2;" : "=f"(r.x), "=f"(r.y) : "l"(v)); return r;
}
__device__ __forceinline__ ull ffma2(ull a, ull b, ull c) {
    ull d; asm("fma.rn.f32x2 %0, %1, %2, %3;" : "=l"(d) : "l"(a), "l"(b), "l"(c)); return d;
}

// ---------------------------- zero scratch ---------------------------------
__global__ void zero_kernel(int n_aggr4, int n) {
    int stride = gridDim.x * blockDim.x;
    int t0 = blockIdx.x * blockDim.x + threadIdx.x;
    float4* a4 = (float4*)g_aggr;
    for (int i = t0; i < n_aggr4; i += stride) a4[i] = make_float4(0.f, 0.f, 0.f, 0.f);
    for (int i = t0; i < n; i += stride) g_cnt[i] = 0.f;
}

// ---------------------------- precompute U, V (proven) ---------------------
#define PNPW 4
#define PWARPS 16
#define PTHREADS 512
#define P_WU  0
#define P_WV  8192
#define P_B1  16384
#define P_BUF 16512
#define P_SMEMF 20608
#define P_SMEMB (P_SMEMF * 4)

__global__ __launch_bounds__(PTHREADS, 1)
void pre_kernel(const float* __restrict__ x, const float* __restrict__ W1,
                const float* __restrict__ b1, int N) {
    extern __shared__ float sm[];
    int tid = threadIdx.x;
    for (int idx = tid; idx < 64 * 128; idx += PTHREADS) {
        float a = W1[idx];
        float b = W1[idx + 64 * 128];
        sm[P_WU + idx] = a - b;
        sm[P_WV + idx] = b;
    }
    for (int t = tid; t < 128; t += PTHREADS) sm[P_B1 + t] = b1[t];
    __syncthreads();

    int warp = tid >> 5, lane = tid & 31;
    float* buf = sm + P_BUF + warp * (PNPW * 64);
    const float* wup = sm + P_WU + lane * 4;
    const float* wvp = sm + P_WV + lane * 4;

    int ngroups = (N + PNPW - 1) / PNPW;
    int gwarp = blockIdx.x * PWARPS + warp;
    int nwarp = gridDim.x * PWARPS;

    for (int g = gwarp; g < ngroups; g += nwarp) {
        int base = g * PNPW;
        #pragma unroll
        for (int u = 0; u < PNPW; u++) {
            int n = base + u;
            if (lane < 16) {
                const float4* xn = (const float4*)(x + (size_t)(n < N ? n : 0) * 64);
                float4 a = (n < N) ? xn[lane] : make_float4(0.f, 0.f, 0.f, 0.f);
                ((float4*)(buf + u * 64))[lane] = a;
            }
        }
        __syncwarp();

        // K-packed: accumulate (even-k, odd-k) partials in f32x2 halves
        ull aU[PNPW][4], aV[PNPW][4];
        #pragma unroll
        for (int u = 0; u < PNPW; u++)
            #pragma unroll
            for (int c = 0; c < 4; c++) { aU[u][c] = 0; aV[u][c] = 0; }

        #pragma unroll 2
        for (int k = 0; k < 64; k += 2) {
            float4 uA = *(const float4*)(wup + k * 128);
            float4 uB = *(const float4*)(wup + (k + 1) * 128);
            float4 vA = *(const float4*)(wvp + k * 128);
            float4 vB = *(const float4*)(wvp + (k + 1) * 128);
            ull u0 = pk2(uA.x, uB.x), u1 = pk2(uA.y, uB.y);
            ull u2 = pk2(uA.z, uB.z), u3 = pk2(uA.w, uB.w);
            ull v0 = pk2(vA.x, vB.x), v1 = pk2(vA.y, vB.y);
            ull v2 = pk2(vA.z, vB.z), v3 = pk2(vA.w, vB.w);
            #pragma unroll
            for (int u = 0; u < PNPW; u++) {
                ull xv = *(const ull*)(buf + u * 64 + k);
                aU[u][0] = ffma2(u0, xv, aU[u][0]);
                aU[u][1] = ffma2(u1, xv, aU[u][1]);
                aU[u][2] = ffma2(u2, xv, aU[u][2]);
                aU[u][3] = ffma2(u3, xv, aU[u][3]);
                aV[u][0] = ffma2(v0, xv, aV[u][0]);
                aV[u][1] = ffma2(v1, xv, aV[u][1]);
                aV[u][2] = ffma2(v2, xv, aV[u][2]);
                aV[u][3] = ffma2(v3, xv, aV[u][3]);
            }
        }
        float bb0 = sm[P_B1 + lane*4],     bb1 = sm[P_B1 + lane*4 + 1];
        float bb2 = sm[P_B1 + lane*4 + 2], bb3 = sm[P_B1 + lane*4 + 3];
        #pragma unroll
        for (int u = 0; u < PNPW; u++) {
            int n = base + u;
            if (n < N) {
                float2 t0 = upk2(aU[u][0]), t1 = upk2(aU[u][1]);
                float2 t2 = upk2(aU[u][2]), t3 = upk2(aU[u][3]);
                *(float4*)(g_u + (size_t)n * 128 + lane * 4) =
                    make_float4(t0.x + t0.y + bb0, t1.x + t1.y + bb1,
                                t2.x + t2.y + bb2, t3.x + t3.y + bb3);
                t0 = upk2(aV[u][0]); t1 = upk2(aV[u][1]);
                t2 = upk2(aV[u][2]); t3 = upk2(aV[u][3]);
                *(float4*)(g_v + (size_t)n * 128 + lane * 4) =
                    make_float4(t0.x + t0.y, t1.x + t1.y, t2.x + t2.y, t3.x + t3.y);
            }
        }
        __syncwarp();
    }
}

// ---------------------------- edge kernel ----------------------------------
#define EPW 8
#define EWARPS 16
#define ETHREADS 512
#define E_WP   0            // 3*128 rel-pos weight rows
#define E_W2   384          // 128*64
#define E_B2   8576         // 64
#define E_BUF  8640         // 16 warps * 8 edges * 128
#define E_IDX  25024        // 16 warps * 8 ints
#define E_SMEMF 25152
#define E_SMEMB (E_SMEMF * 4)

__global__ __launch_bounds__(ETHREADS, 1)
void edge_kernel(const float* __restrict__ pos,
                 const int* __restrict__ idxI, const int* __restrict__ idxJ,
                 const float* __restrict__ W1, const float* __restrict__ W2,
                 const float* __restrict__ b2, int E) {
    extern __shared__ float sm[];
    int tid = threadIdx.x;

    for (int t = tid; t < 384; t += ETHREADS) sm[E_WP + t] = W1[128 * 128 + t];
    {
        float4* d2 = (float4*)(sm + E_W2); const float4* s2 = (const float4*)W2;
        for (int t = tid; t < 2048; t += ETHREADS) d2[t] = s2[t];
        float4* d3 = (float4*)(sm + E_B2); const float4* s3 = (const float4*)b2;
        for (int t = tid; t < 16; t += ETHREADS) d3[t] = s3[t];
    }
    __syncthreads();

    int warp = tid >> 5, lane = tid & 31;
    float* buf = sm + E_BUF + warp * (EPW * 128);
    int* sidx = (int*)(sm + E_IDX) + warp * EPW;

    const float* w2p = sm + E_W2 + lane*2;
    float bz0 = sm[E_B2 + lane*2], bz1 = sm[E_B2 + lane*2 + 1];
    float4 wp0 = *(const float4*)(sm + E_WP + 0 * 128 + lane * 4);
    float4 wp1 = *(const float4*)(sm + E_WP + 1 * 128 + lane * 4);
    float4 wp2 = *(const float4*)(sm + E_WP + 2 * 128 + lane * 4);

    int ngroups = (E + EPW - 1) / EPW;
    int gwarp = blockIdx.x * EWARPS + warp;
    int nwarp = gridDim.x * EWARPS;

    for (int g = gwarp; g < ngroups; g += nwarp) {
        int base = g * EPW;

        // ---- batch index loads ----
        int ii[EPW], jj[EPW];
        #pragma unroll
        for (int e = 0; e < EPW; e++) {
            int ei = base + e;
            bool ok = ei < E;
            ii[e] = ok ? idxI[ei] : -1;
            jj[e] = ok ? idxJ[ei] : 0;
        }
        if (lane == 0) {
            #pragma unroll
            for (int e = 0; e < EPW; e++) sidx[e] = ii[e];
        }

        // ---- batch U/V/pos gathers, compute hidden ----
        float4 uu[EPW], vv[EPW];
        float p0v[EPW], p1v[EPW], p2v[EPW];
        #pragma unroll
        for (int e = 0; e < EPW; e++) {
            int i = (ii[e] >= 0) ? ii[e] : 0;
            int j = jj[e];
            uu[e] = *(const float4*)(g_u + (size_t)i * 128 + lane * 4);
            vv[e] = *(const float4*)(g_v + (size_t)j * 128 + lane * 4);
            p0v[e] = pos[(size_t)j*3 + 0] - pos[(size_t)i*3 + 0];
            p1v[e] = pos[(size_t)j*3 + 1] - pos[(size_t)i*3 + 1];
            p2v[e] = pos[(size_t)j*3 + 2] - pos[(size_t)i*3 + 2];
        }
        #pragma unroll
        for (int e = 0; e < EPW; e++) {
            if (ii[e] >= 0) {
                float4 h;
                h.x = uu[e].x + vv[e].x + p0v[e]*wp0.x + p1v[e]*wp1.x + p2v[e]*wp2.x;
                h.y = uu[e].y + vv[e].y + p0v[e]*wp0.y + p1v[e]*wp1.y + p2v[e]*wp2.y;
                h.z = uu[e].z + vv[e].z + p0v[e]*wp0.z + p1v[e]*wp1.z + p2v[e]*wp2.z;
                h.w = uu[e].w + vv[e].w + p0v[e]*wp0.w + p1v[e]*wp1.w + p2v[e]*wp2.w;
                *(float4*)(buf + e*128 + lane*4) =
                    make_float4(fmaxf(h.x,0.f), fmaxf(h.y,0.f), fmaxf(h.z,0.f), fmaxf(h.w,0.f));
            } else {
                *(float4*)(buf + e*128 + lane*4) = make_float4(0.f, 0.f, 0.f, 0.f);
            }
        }
        __syncwarp();

        // ---- msg = hidden @ W2 + b2 ; K-packed f32x2, lane owns cols 2l,2l+1
        ull mA[EPW], mB[EPW];
        #pragma unroll
        for (int e = 0; e < EPW; e++) { mA[e] = 0; mB[e] = 0; }
        #pragma unroll 2
        for (int k = 0; k < 128; k += 2) {
            float2 wA = *(const float2*)(w2p + k * 64);
            float2 wB = *(const float2*)(w2p + (k + 1) * 64);
            ull w0 = pk2(wA.x, wB.x);   // col c0: (w[k], w[k+1])
            ull w1 = pk2(wA.y, wB.y);   // col c1
            #pragma unroll
            for (int e = 0; e < EPW; e++) {
                ull h = *(const ull*)(buf + e*128 + k);   // (h[k], h[k+1])
                mA[e] = ffma2(w0, h, mA[e]);
                mB[e] = ffma2(w1, h, mB[e]);
            }
        }

        // ---- scatter-add: scalar atomics (proven) ----
        #pragma unroll
        for (int e = 0; e < EPW; e++) {
            int i = sidx[e];
            if (i >= 0) {
                float2 a = upk2(mA[e]);
                float2 b = upk2(mB[e]);
                float* dst = g_aggr + (size_t)i * 64 + lane * 2;
                atomicAdd(dst,     a.x + a.y + bz0);
                atomicAdd(dst + 1, b.x + b.y + bz1);
            }
        }
        if (lane < EPW) {
            int i = sidx[lane];
            if (i >= 0) atomicAdd(g_cnt + i, 1.0f);
        }
        __syncwarp();
    }
}

// ---------------------------- node kernel (K-packed) -----------------------
#define NPW 4
#define NWARPS 16
#define NTHREADS 512
#define N_W3   0
#define N_B3   16384
#define N_W4   16512
#define N_B4   24704
#define N_BUF  24768       // 16 warps * 4 nodes * 128
#define N_SMEMF 32960
#define N_SMEMB (N_SMEMF * 4)

__global__ __launch_bounds__(NTHREADS, 1)
void node_kernel(const float* __restrict__ x,
                 const float* __restrict__ W3, const float* __restrict__ b3,
                 const float* __restrict__ W4, const float* __restrict__ b4,
                 float* __restrict__ out, int N) {
    extern __shared__ float sm[];
    int tid = threadIdx.x;
    {
        float4* d = (float4*)(sm + N_W3); const float4* s = (const float4*)W3;
        for (int t = tid; t < 4096; t += NTHREADS) d[t] = s[t];
        float4* d1 = (float4*)(sm + N_B3); const float4* s1 = (const float4*)b3;
        for (int t = tid; t < 32; t += NTHREADS) d1[t] = s1[t];
        float4* d2 = (float4*)(sm + N_W4); const float4* s2 = (const float4*)W4;
        for (int t = tid; t < 2048; t += NTHREADS) d2[t] = s2[t];
        float4* d3 = (float4*)(sm + N_B4); const float4* s3 = (const float4*)b4;
        for (int t = tid; t < 16; t += NTHREADS) d3[t] = s3[t];
    }
    __syncthreads();

    int warp = tid >> 5, lane = tid & 31;
    float* buf = sm + N_BUF + warp * (NPW * 128);
    const float* w3p = sm + N_W3 + lane*4;
    const float* w4p = sm + N_W4 + lane*2;
    float hb0 = sm[N_B3 + lane*4],     hb1 = sm[N_B3 + lane*4 + 1];
    float hb2 = sm[N_B3 + lane*4 + 2], hb3 = sm[N_B3 + lane*4 + 3];
    float ob0 = sm[N_B4 + lane*2],     ob1 = sm[N_B4 + lane*2 + 1];

    int ngroups = (N + NPW - 1) / NPW;
    int gwarp = blockIdx.x * NWARPS + warp;
    int nwarp = gridDim.x * NWARPS;

    for (int g = gwarp; g < ngroups; g += nwarp) {
        int base = g * NPW;

        #pragma unroll
        for (int u = 0; u < NPW; u++) {
            int n = base + u;
            if (n < N) {
                if (lane < 16) {
                    float inv = 1.0f / fmaxf(g_cnt[n], 1.0f);
                    const float4* xn = (const float4*)(x + (size_t)n * 64);
                    const float4* an = (const float4*)(g_aggr + (size_t)n * 64);
                    float4 a = xn[lane], b = an[lane];
                    float4* pb = (float4*)(buf + u * 128);
                    pb[lane] = a;
                    pb[16 + lane] = make_float4(b.x*inv, b.y*inv, b.z*inv, b.w*inv);
                }
            } else {
                for (int t = lane; t < 128; t += 32) buf[u*128 + t] = 0.f;
            }
        }
        __syncwarp();

        // phase 1: relu(upd_in @ W3 + b3), K-packed; lane owns cols 4l..4l+3
        ull a[NPW][4];
        #pragma unroll
        for (int u = 0; u < NPW; u++)
            #pragma unroll
            for (int c = 0; c < 4; c++) a[u][c] = 0;
        #pragma unroll 2
        for (int k = 0; k < 128; k += 2) {
            float4 wA = *(const float4*)(w3p + k * 128);
            float4 wB = *(const float4*)(w3p + (k + 1) * 128);
            ull w0 = pk2(wA.x, wB.x), w1 = pk2(wA.y, wB.y);
            ull w2 = pk2(wA.z, wB.z), w3 = pk2(wA.w, wB.w);
            #pragma unroll
            for (int u = 0; u < NPW; u++) {
                ull v = *(const ull*)(buf + u*128 + k);
                a[u][0] = ffma2(w0, v, a[u][0]);
                a[u][1] = ffma2(w1, v, a[u][1]);
                a[u][2] = ffma2(w2, v, a[u][2]);
                a[u][3] = ffma2(w3, v, a[u][3]);
            }
        }
        __syncwarp();
        #pragma unroll
        for (int u = 0; u < NPW; u++) {
            float2 t0 = upk2(a[u][0]), t1 = upk2(a[u][1]);
            float2 t2 = upk2(a[u][2]), t3 = upk2(a[u][3]);
            *(float4*)(buf + u*128 + lane*4) =
                make_float4(fmaxf(t0.x + t0.y + hb0, 0.f),
                            fmaxf(t1.x + t1.y + hb1, 0.f),
                            fmaxf(t2.x + t2.y + hb2, 0.f),
                            fmaxf(t3.x + t3.y + hb3, 0.f));
        }
        __syncwarp();

        // phase 2: out = hidden @ W4 + b4, K-packed; lane owns cols 2l,2l+1
        ull mA[NPW], mB[NPW];
        #pragma unroll
        for (int u = 0; u < NPW; u++) { mA[u] = 0; mB[u] = 0; }
        #pragma unroll 2
        for (int k = 0; k < 128; k += 2) {
            float2 wA = *(const float2*)(w4p + k * 64);
            float2 wB = *(const float2*)(w4p + (k + 1) * 64);
            ull w0 = pk2(wA.x, wB.x);
            ull w1 = pk2(wA.y, wB.y);
            #pragma unroll
            for (int u = 0; u < NPW; u++) {
                ull h = *(const ull*)(buf + u*128 + k);
                mA[u] = ffma2(w0, h, mA[u]);
                mB[u] = ffma2(w1, h, mB[u]);
            }
        }
        #pragma unroll
        for (int u = 0; u < NPW; u++) {
            int n = base + u;
            if (n < N) {
                float2 a2 = upk2(mA[u]);
                float2 b2v = upk2(mB[u]);
                *(float2*)(out + (size_t)n * 64 + lane * 2) =
                    make_float2(a2.x + a2.y + ob0, b2v.x + b2v.y + ob1);
            }
        }
        __syncwarp();
    }
}

// ---------------------------- launch ---------------------------------------
extern "C" void kernel_launch(void* const* d_in, const int* in_sizes, int n_in,
                              void* d_out, int out_size) {
    const float* x   = (const float*)d_in[0];
    const float* pos = (const float*)d_in[1];
    const int*   ei  = (const int*)d_in[2];
    const float* W1  = (const float*)d_in[3];
    const float* b1  = (const float*)d_in[4];
    const float* W2  = (const float*)d_in[5];
    const float* b2  = (const float*)d_in[6];
    const float* W3  = (const float*)d_in[7];
    const float* b3  = (const float*)d_in[8];
    const float* W4  = (const float*)d_in[9];
    const float* b4  = (const float*)d_in[10];
    int N = in_sizes[0] / 64;
    int E = in_sizes[2] / 2;

    cudaFuncSetAttribute(pre_kernel,  cudaFuncAttributeMaxDynamicSharedMemorySize, P_SMEMB);
    cudaFuncSetAttribute(edge_kernel, cudaFuncAttributeMaxDynamicSharedMemorySize, E_SMEMB);
    cudaFuncSetAttribute(node_kernel, cudaFuncAttributeMaxDynamicSharedMemorySize, N_SMEMB);

    zero_kernel<<<512, 256>>>(N * 16, N);
    pre_kernel<<<304, PTHREADS, P_SMEMB>>>(x, W1, b1, N);
    edge_kernel<<<304, ETHREADS, E_SMEMB>>>(pos, ei, ei + E, W1, W2, b2, E);
    node_kernel<<<304, NTHREADS, N_SMEMB>>>(x, W3, b3, W4, b4, (float*)d_out, N);
}

// round 11
// speedup vs baseline: 1.5799x; 1.5799x over previous
#include <cuda_runtime.h>
#include <cstdint>

// ---------------------------------------------------------------------------
// MPNN layer, fully hoisted:
//   K0: zero aggr(128-dim)/cnt
//   Kw23: W23 = W2 @ W3[64:128], cb = b2 @ W3[64:128]
//   Kpre: U = x@(W1a-W1b)+b1, V = x@W1b, A = x@W3[0:64]+b3
//   Kedge: h = relu(U[i]+V[j]+relpos@W1p); scatter-add h (128-dim) + cnt
//          -> NO GEMM in the edge loop at all
//   Knode: meanh = aggr/max(cnt,1); relu(meanh@W23 + A + flag*cb) @ W4 + b4
// All GEMM loops use the R9-proven f32x2 broadcast style (no cross-reg packs).
// ---------------------------------------------------------------------------

#define MAXN 65536
__device__ float g_aggr[MAXN * 128];
__device__ float g_cnt[MAXN];
__device__ float g_u[MAXN * 128];
__device__ float g_v[MAXN * 128];
__device__ float g_a[MAXN * 128];
__device__ float g_w23[128 * 128];
__device__ float g_cb[128];

typedef unsigned long long ull;

__device__ __forceinline__ ull pk2(float a, float b) {
    ull r; asm("mov.b64 %0, {%1, %2};" : "=l"(r) : "f"(a), "f"(b)); return r;
}
__device__ __forceinline__ float2 upk2(ull v) {
    float2 r; asm("mov.b64 {%0, %1}, %2;" : "=f"(r.x), "=f"(r.y) : "l"(v)); return r;
}
__device__ __forceinline__ ull ffma2(ull a, ull b, ull c) {
    ull d; asm("fma.rn.f32x2 %0, %1, %2, %3;" : "=l"(d) : "l"(a), "l"(b), "l"(c)); return d;
}

// ---------------------------- zero scratch ---------------------------------
__global__ void zero_kernel(int n_aggr4, int n) {
    int stride = gridDim.x * blockDim.x;
    int t0 = blockIdx.x * blockDim.x + threadIdx.x;
    float4* a4 = (float4*)g_aggr;
    for (int i = t0; i < n_aggr4; i += stride) a4[i] = make_float4(0.f, 0.f, 0.f, 0.f);
    for (int i = t0; i < n; i += stride) g_cnt[i] = 0.f;
}

// ---------------------------- W23 = W2 @ W3a, cb = b2 @ W3a ----------------
__global__ void w23_kernel(const float* __restrict__ W2, const float* __restrict__ b2,
                           const float* __restrict__ W3) {
    int c = threadIdx.x;            // 128 threads
    int k = blockIdx.x;             // 0..128 (128 == cb row)
    float s = 0.f;
    if (k < 128) {
        #pragma unroll 8
        for (int m = 0; m < 64; m++) s += W2[k * 64 + m] * W3[(64 + m) * 128 + c];
        g_w23[k * 128 + c] = s;
    } else {
        #pragma unroll 8
        for (int m = 0; m < 64; m++) s += b2[m] * W3[(64 + m) * 128 + c];
        g_cb[c] = s;
    }
}

// ---------------------------- precompute U, V, A ---------------------------
// U = x@(W1[0:64]-W1[64:128]) + b1 ; V = x@W1[64:128] ; A = x@W3[0:64] + b3
#define PNPW 2
#define PWARPS 16
#define PTHREADS 512
#define P_WU  0            // 64*128
#define P_WV  8192
#define P_WA  16384
#define P_B1  24576        // 128
#define P_B3  24704        // 128
#define P_BUF 24832        // 16 warps * 2 nodes * 64
#define P_SMEMF 26880
#define P_SMEMB (P_SMEMF * 4)

__global__ __launch_bounds__(PTHREADS, 1)
void pre_kernel(const float* __restrict__ x, const float* __restrict__ W1,
                const float* __restrict__ b1, const float* __restrict__ W3,
                const float* __restrict__ b3, int N) {
    extern __shared__ float sm[];
    int tid = threadIdx.x;
    for (int idx = tid; idx < 64 * 128; idx += PTHREADS) {
        float a = W1[idx];
        float b = W1[idx + 64 * 128];
        sm[P_WU + idx] = a - b;
        sm[P_WV + idx] = b;
        sm[P_WA + idx] = W3[idx];
    }
    for (int t = tid; t < 128; t += PTHREADS) { sm[P_B1 + t] = b1[t]; sm[P_B3 + t] = b3[t]; }
    __syncthreads();

    int warp = tid >> 5, lane = tid & 31;
    float* buf = sm + P_BUF + warp * (PNPW * 64);
    const float* wup = sm + P_WU + lane * 4;
    const float* wvp = sm + P_WV + lane * 4;
    const float* wap = sm + P_WA + lane * 4;

    ull ub0 = pk2(sm[P_B1 + lane*4],     sm[P_B1 + lane*4 + 1]);
    ull ub1 = pk2(sm[P_B1 + lane*4 + 2], sm[P_B1 + lane*4 + 3]);
    ull ab0 = pk2(sm[P_B3 + lane*4],     sm[P_B3 + lane*4 + 1]);
    ull ab1 = pk2(sm[P_B3 + lane*4 + 2], sm[P_B3 + lane*4 + 3]);

    int ngroups = (N + PNPW - 1) / PNPW;
    int gwarp = blockIdx.x * PWARPS + warp;
    int nwarp = gridDim.x * PWARPS;

    for (int g = gwarp; g < ngroups; g += nwarp) {
        int base = g * PNPW;
        #pragma unroll
        for (int u = 0; u < PNPW; u++) {
            int n = base + u;
            if (lane < 16) {
                const float4* xn = (const float4*)(x + (size_t)(n < N ? n : 0) * 64);
                float4 a = (n < N) ? xn[lane] : make_float4(0.f, 0.f, 0.f, 0.f);
                ((float4*)(buf + u * 64))[lane] = a;
            }
        }
        __syncwarp();

        ull aU0[PNPW], aU1[PNPW], aV0[PNPW], aV1[PNPW], aA0[PNPW], aA1[PNPW];
        #pragma unroll
        for (int u = 0; u < PNPW; u++) {
            aU0[u] = ub0; aU1[u] = ub1; aV0[u] = 0; aV1[u] = 0; aA0[u] = ab0; aA1[u] = ab1;
        }

        #pragma unroll 2
        for (int k = 0; k < 64; k += 2) {
            float4 uA = *(const float4*)(wup + k * 128);
            float4 uB = *(const float4*)(wup + (k + 1) * 128);
            float4 vA = *(const float4*)(wvp + k * 128);
            float4 vB = *(const float4*)(wvp + (k + 1) * 128);
            float4 wA = *(const float4*)(wap + k * 128);
            float4 wB = *(const float4*)(wap + (k + 1) * 128);
            ull uA01 = pk2(uA.x, uA.y), uA23 = pk2(uA.z, uA.w);
            ull uB01 = pk2(uB.x, uB.y), uB23 = pk2(uB.z, uB.w);
            ull vA01 = pk2(vA.x, vA.y), vA23 = pk2(vA.z, vA.w);
            ull vB01 = pk2(vB.x, vB.y), vB23 = pk2(vB.z, vB.w);
            ull wA01 = pk2(wA.x, wA.y), wA23 = pk2(wA.z, wA.w);
            ull wB01 = pk2(wB.x, wB.y), wB23 = pk2(wB.z, wB.w);
            #pragma unroll
            for (int u = 0; u < PNPW; u++) {
                float2 xv = *(const float2*)(buf + u * 64 + k);
                ull x0 = pk2(xv.x, xv.x);
                ull x1 = pk2(xv.y, xv.y);
                aU0[u] = ffma2(uA01, x0, aU0[u]);
                aU1[u] = ffma2(uA23, x0, aU1[u]);
                aV0[u] = ffma2(vA01, x0, aV0[u]);
                aV1[u] = ffma2(vA23, x0, aV1[u]);
                aA0[u] = ffma2(wA01, x0, aA0[u]);
                aA1[u] = ffma2(wA23, x0, aA1[u]);
                aU0[u] = ffma2(uB01, x1, aU0[u]);
                aU1[u] = ffma2(uB23, x1, aU1[u]);
                aV0[u] = ffma2(vB01, x1, aV0[u]);
                aV1[u] = ffma2(vB23, x1, aV1[u]);
                aA0[u] = ffma2(wB01, x1, aA0[u]);
                aA1[u] = ffma2(wB23, x1, aA1[u]);
            }
        }
        #pragma unroll
        for (int u = 0; u < PNPW; u++) {
            int n = base + u;
            if (n < N) {
                float2 p, q;
                p = upk2(aU0[u]); q = upk2(aU1[u]);
                *(float4*)(g_u + (size_t)n * 128 + lane * 4) = make_float4(p.x, p.y, q.x, q.y);
                p = upk2(aV0[u]); q = upk2(aV1[u]);
                *(float4*)(g_v + (size_t)n * 128 + lane * 4) = make_float4(p.x, p.y, q.x, q.y);
                p = upk2(aA0[u]); q = upk2(aA1[u]);
                *(float4*)(g_a + (size_t)n * 128 + lane * 4) = make_float4(p.x, p.y, q.x, q.y);
            }
        }
        __syncwarp();
    }
}

// ---------------------------- edge kernel (no GEMM) ------------------------
#define EPW 8
#define EWARPS 16
#define ETHREADS 512
#define E_SMEMF 384        // 3*128 rel-pos weight rows only
#define E_SMEMB (E_SMEMF * 4)

__global__ __launch_bounds__(ETHREADS, 1)
void edge_kernel(const float* __restrict__ pos,
                 const int* __restrict__ idxI, const int* __restrict__ idxJ,
                 const float* __restrict__ W1, int E) {
    extern __shared__ float sm[];
    int tid = threadIdx.x;
    for (int t = tid; t < 384; t += ETHREADS) sm[t] = W1[128 * 128 + t];
    __syncthreads();

    int warp = tid >> 5, lane = tid & 31;
    float4 wp0 = *(const float4*)(sm + 0 * 128 + lane * 4);
    float4 wp1 = *(const float4*)(sm + 1 * 128 + lane * 4);
    float4 wp2 = *(const float4*)(sm + 2 * 128 + lane * 4);

    int ngroups = (E + EPW - 1) / EPW;
    int gwarp = blockIdx.x * EWARPS + warp;
    int nwarp = gridDim.x * EWARPS;

    for (int g = gwarp; g < ngroups; g += nwarp) {
        int base = g * EPW;

        // batch index loads (all LDGs in flight together)
        int ii[EPW], jj[EPW];
        #pragma unroll
        for (int e = 0; e < EPW; e++) {
            int ei = base + e;
            bool ok = ei < E;
            ii[e] = ok ? idxI[ei] : -1;
            jj[e] = ok ? idxJ[ei] : 0;
        }

        // batch U/V/pos gathers
        float4 uu[EPW], vv[EPW];
        float p0v[EPW], p1v[EPW], p2v[EPW];
        #pragma unroll
        for (int e = 0; e < EPW; e++) {
            int i = (ii[e] >= 0) ? ii[e] : 0;
            int j = jj[e];
            uu[e] = *(const float4*)(g_u + (size_t)i * 128 + lane * 4);
            vv[e] = *(const float4*)(g_v + (size_t)j * 128 + lane * 4);
            p0v[e] = pos[(size_t)j*3 + 0] - pos[(size_t)i*3 + 0];
            p1v[e] = pos[(size_t)j*3 + 1] - pos[(size_t)i*3 + 1];
            p2v[e] = pos[(size_t)j*3 + 2] - pos[(size_t)i*3 + 2];
        }

        // h = relu(U+V+rp@W1p), scatter-add 128-dim hidden + cnt
        #pragma unroll
        for (int e = 0; e < EPW; e++) {
            int i = ii[e];
            if (i >= 0) {
                float hx = fmaxf(uu[e].x + vv[e].x + p0v[e]*wp0.x + p1v[e]*wp1.x + p2v[e]*wp2.x, 0.f);
                float hy = fmaxf(uu[e].y + vv[e].y + p0v[e]*wp0.y + p1v[e]*wp1.y + p2v[e]*wp2.y, 0.f);
                float hz = fmaxf(uu[e].z + vv[e].z + p0v[e]*wp0.z + p1v[e]*wp1.z + p2v[e]*wp2.z, 0.f);
                float hw = fmaxf(uu[e].w + vv[e].w + p0v[e]*wp0.w + p1v[e]*wp1.w + p2v[e]*wp2.w, 0.f);
                float* dst = g_aggr + (size_t)i * 128 + lane * 4;
                atomicAdd(dst + 0, hx);
                atomicAdd(dst + 1, hy);
                atomicAdd(dst + 2, hz);
                atomicAdd(dst + 3, hw);
                if (lane == 0) atomicAdd(g_cnt + i, 1.0f);
            }
        }
    }
}

// ---------------------------- node kernel ----------------------------------
// hupd = relu(meanh @ W23 + A[n] + flag*cb); out = hupd @ W4 + b4
#define NPW 8
#define NWARPS 16
#define NTHREADS 512
#define N_W23  0           // 128*128
#define N_CB   16384       // 128
#define N_W4   16512       // 128*64
#define N_B4   24704       // 64
#define N_BUF  24768       // 16 warps * 8 nodes * 128
#define N_SMEMF 41152
#define N_SMEMB (N_SMEMF * 4)

__global__ __launch_bounds__(NTHREADS, 1)
void node_kernel(const float* __restrict__ W4, const float* __restrict__ b4,
                 float* __restrict__ out, int N) {
    extern __shared__ float sm[];
    int tid = threadIdx.x;
    {
        float4* d = (float4*)(sm + N_W23); const float4* s = (const float4*)g_w23;
        for (int t = tid; t < 4096; t += NTHREADS) d[t] = s[t];
        float4* d1 = (float4*)(sm + N_CB); const float4* s1 = (const float4*)g_cb;
        for (int t = tid; t < 32; t += NTHREADS) d1[t] = s1[t];
        float4* d2 = (float4*)(sm + N_W4); const float4* s2 = (const float4*)W4;
        for (int t = tid; t < 2048; t += NTHREADS) d2[t] = s2[t];
        float4* d3 = (float4*)(sm + N_B4); const float4* s3 = (const float4*)b4;
        for (int t = tid; t < 16; t += NTHREADS) d3[t] = s3[t];
    }
    __syncthreads();

    int warp = tid >> 5, lane = tid & 31;
    float* buf = sm + N_BUF + warp * (NPW * 128);
    const float* w3p = sm + N_W23 + lane*4;
    const float* w4p = sm + N_W4 + lane*2;
    float4 cb4 = *(const float4*)(sm + N_CB + lane * 4);
    ull ob = pk2(sm[N_B4 + lane*2], sm[N_B4 + lane*2 + 1]);

    int ngroups = (N + NPW - 1) / NPW;
    int gwarp = blockIdx.x * NWARPS + warp;
    int nwarp = gridDim.x * NWARPS;

    for (int g = gwarp; g < ngroups; g += nwarp) {
        int base = g * NPW;

        // gather meanh = aggr/max(cnt,1); record flag (cnt>0)
        float flg[NPW];
        #pragma unroll
        for (int u = 0; u < NPW; u++) {
            int n = base + u;
            if (n < N) {
                float c = g_cnt[n];
                flg[u] = (c > 0.f) ? 1.0f : 0.0f;
                float inv = 1.0f / fmaxf(c, 1.0f);
                const float4* an = (const float4*)(g_aggr + (size_t)n * 128);
                float4 b = an[lane];
                ((float4*)(buf + u * 128))[lane] =
                    make_float4(b.x*inv, b.y*inv, b.z*inv, b.w*inv);
            } else {
                flg[u] = 0.f;
                ((float4*)(buf + u * 128))[lane] = make_float4(0.f, 0.f, 0.f, 0.f);
            }
        }
        __syncwarp();

        // phase 1: meanh @ W23 (R9-proven broadcast f32x2 loop)
        ull a0[NPW], a1[NPW];
        #pragma unroll
        for (int u = 0; u < NPW; u++) { a0[u] = 0; a1[u] = 0; }
        #pragma unroll 2
        for (int k = 0; k < 128; k += 2) {
            float4 wA = *(const float4*)(w3p + k * 128);
            float4 wB = *(const float4*)(w3p + (k + 1) * 128);
            ull wA01 = pk2(wA.x, wA.y), wA23 = pk2(wA.z, wA.w);
            ull wB01 = pk2(wB.x, wB.y), wB23 = pk2(wB.z, wB.w);
            #pragma unroll
            for (int u = 0; u < NPW; u++) {
                float2 v = *(const float2*)(buf + u*128 + k);
                ull v0 = pk2(v.x, v.x);
                ull v1 = pk2(v.y, v.y);
                a0[u] = ffma2(wA01, v0, a0[u]);
                a1[u] = ffma2(wA23, v0, a1[u]);
                a0[u] = ffma2(wB01, v1, a0[u]);
                a1[u] = ffma2(wB23, v1, a1[u]);
            }
        }
        __syncwarp();

        // epilogue: + A[n] + flag*cb, relu -> buf
        float4 A4[NPW];
        #pragma unroll
        for (int u = 0; u < NPW; u++) {
            int n = base + u;
            A4[u] = *(const float4*)(g_a + (size_t)(n < N ? n : 0) * 128 + lane * 4);
        }
        #pragma unroll
        for (int u = 0; u < NPW; u++) {
            float2 p = upk2(a0[u]);
            float2 q = upk2(a1[u]);
            float f = flg[u];
            *(float4*)(buf + u*128 + lane*4) = make_float4(
                fmaxf(p.x + A4[u].x + f*cb4.x, 0.f),
                fmaxf(p.y + A4[u].y + f*cb4.y, 0.f),
                fmaxf(q.x + A4[u].z + f*cb4.z, 0.f),
                fmaxf(q.y + A4[u].w + f*cb4.w, 0.f));
        }
        __syncwarp();

        // phase 2: out = hupd @ W4 + b4 (R9-proven)
        ull m[NPW];
        #pragma unroll
        for (int u = 0; u < NPW; u++) m[u] = ob;
        #pragma unroll 2
        for (int k = 0; k < 128; k += 2) {
            float2 wA = *(const float2*)(w4p + k * 64);
            float2 wB = *(const float2*)(w4p + (k + 1) * 64);
            ull wAp = pk2(wA.x, wA.y);
            ull wBp = pk2(wB.x, wB.y);
            #pragma unroll
            for (int u = 0; u < NPW; u++) {
                float2 h = *(const float2*)(buf + u*128 + k);
                m[u] = ffma2(wAp, pk2(h.x, h.x), m[u]);
                m[u] = ffma2(wBp, pk2(h.y, h.y), m[u]);
            }
        }
        #pragma unroll
        for (int u = 0; u < NPW; u++) {
            int n = base + u;
            if (n < N) {
                float2 rr = upk2(m[u]);
                *(float2*)(out + (size_t)n * 64 + lane * 2) = rr;
            }
        }
        __syncwarp();
    }
}

// ---------------------------- launch ---------------------------------------
extern "C" void kernel_launch(void* const* d_in, const int* in_sizes, int n_in,
                              void* d_out, int out_size) {
    const float* x   = (const float*)d_in[0];
    const float* pos = (const float*)d_in[1];
    const int*   ei  = (const int*)d_in[2];
    const float* W1  = (const float*)d_in[3];
    const float* b1  = (const float*)d_in[4];
    const float* W2  = (const float*)d_in[5];
    const float* b2  = (const float*)d_in[6];
    const float* W3  = (const float*)d_in[7];
    const float* b3  = (const float*)d_in[8];
    const float* W4  = (const float*)d_in[9];
    const float* b4  = (const float*)d_in[10];
    int N = in_sizes[0] / 64;
    int E = in_sizes[2] / 2;

    cudaFuncSetAttribute(pre_kernel,  cudaFuncAttributeMaxDynamicSharedMemorySize, P_SMEMB);
    cudaFuncSetAttribute(edge_kernel, cudaFuncAttributeMaxDynamicSharedMemorySize, E_SMEMB);
    cudaFuncSetAttribute(node_kernel, cudaFuncAttributeMaxDynamicSharedMemorySize, N_SMEMB);

    zero_kernel<<<512, 256>>>(N * 32, N);
    w23_kernel<<<129, 128>>>(W2, b2, W3);
    pre_kernel<<<304, PTHREADS, P_SMEMB>>>(x, W1, b1, W3, b3, N);
    edge_kernel<<<304, ETHREADS, E_SMEMB>>>(pos, ei, ei + E, W1, E);
    node_kernel<<<304, NTHREADS, N_SMEMB>>>(W4, b4, (float*)d_out, N);
}

// round 15
// speedup vs baseline: 1.5873x; 1.0047x over previous
#include <cuda_runtime.h>
#include <cstdint>

// ---------------------------------------------------------------------------
// MPNN layer, fully hoisted (R11 structure, edge kernel 256-thr/EPW=4):
//   K0: zero aggr(128-dim)/cnt
//   Kw23: W23 = W2 @ W3[64:128], cb = b2 @ W3[64:128]
//   Kpre: U = x@(W1a-W1b)+b1, V = x@W1b, A = x@W3[0:64]+b3
//   Kedge: h = relu(U[i]+V[j]+relpos@W1p); scatter-add h (128-dim) + cnt
//          256 thr/CTA, EPW=4, NO min-blocks hint (suspected container-killer)
//   Knode: meanh = aggr/max(cnt,1); relu(meanh@W23 + A + flag*cb) @ W4 + b4
// ---------------------------------------------------------------------------

#define MAXN 65536
__device__ float g_aggr[MAXN * 128];
__device__ float g_cnt[MAXN];
__device__ float g_u[MAXN * 128];
__device__ float g_v[MAXN * 128];
__device__ float g_a[MAXN * 128];
__device__ float g_w23[128 * 128];
__device__ float g_cb[128];

typedef unsigned long long ull;

__device__ __forceinline__ ull pk2(float a, float b) {
    ull r; asm("mov.b64 %0, {%1, %2};" : "=l"(r) : "f"(a), "f"(b)); return r;
}
__device__ __forceinline__ float2 upk2(ull v) {
    float2 r; asm("mov.b64 {%0, %1}, %2;" : "=f"(r.x), "=f"(r.y) : "l"(v)); return r;
}
__device__ __forceinline__ ull ffma2(ull a, ull b, ull c) {
    ull d; asm("fma.rn.f32x2 %0, %1, %2, %3;" : "=l"(d) : "l"(a), "l"(b), "l"(c)); return d;
}

// ---------------------------- zero scratch ---------------------------------
__global__ void zero_kernel(int n_aggr4, int n) {
    int stride = gridDim.x * blockDim.x;
    int t0 = blockIdx.x * blockDim.x + threadIdx.x;
    float4* a4 = (float4*)g_aggr;
    for (int i = t0; i < n_aggr4; i += stride) a4[i] = make_float4(0.f, 0.f, 0.f, 0.f);
    for (int i = t0; i < n; i += stride) g_cnt[i] = 0.f;
}

// ---------------------------- W23 = W2 @ W3a, cb = b2 @ W3a ----------------
__global__ void w23_kernel(const float* __restrict__ W2, const float* __restrict__ b2,
                           const float* __restrict__ W3) {
    int c = threadIdx.x;            // 128 threads
    int k = blockIdx.x;             // 0..128 (128 == cb row)
    float s = 0.f;
    if (k < 128) {
        #pragma unroll 8
        for (int m = 0; m < 64; m++) s += W2[k * 64 + m] * W3[(64 + m) * 128 + c];
        g_w23[k * 128 + c] = s;
    } else {
        #pragma unroll 8
        for (int m = 0; m < 64; m++) s += b2[m] * W3[(64 + m) * 128 + c];
        g_cb[c] = s;
    }
}

// ---------------------------- precompute U, V, A ---------------------------
#define PNPW 2
#define PWARPS 16
#define PTHREADS 512
#define P_WU  0
#define P_WV  8192
#define P_WA  16384
#define P_B1  24576
#define P_B3  24704
#define P_BUF 24832
#define P_SMEMF 26880
#define P_SMEMB (P_SMEMF * 4)

__global__ __launch_bounds__(PTHREADS, 1)
void pre_kernel(const float* __restrict__ x, const float* __restrict__ W1,
                const float* __restrict__ b1, const float* __restrict__ W3,
                const float* __restrict__ b3, int N) {
    extern __shared__ float sm[];
    int tid = threadIdx.x;
    for (int idx = tid; idx < 64 * 128; idx += PTHREADS) {
        float a = W1[idx];
        float b = W1[idx + 64 * 128];
        sm[P_WU + idx] = a - b;
        sm[P_WV + idx] = b;
        sm[P_WA + idx] = W3[idx];
    }
    for (int t = tid; t < 128; t += PTHREADS) { sm[P_B1 + t] = b1[t]; sm[P_B3 + t] = b3[t]; }
    __syncthreads();

    int warp = tid >> 5, lane = tid & 31;
    float* buf = sm + P_BUF + warp * (PNPW * 64);
    const float* wup = sm + P_WU + lane * 4;
    const float* wvp = sm + P_WV + lane * 4;
    const float* wap = sm + P_WA + lane * 4;

    ull ub0 = pk2(sm[P_B1 + lane*4],     sm[P_B1 + lane*4 + 1]);
    ull ub1 = pk2(sm[P_B1 + lane*4 + 2], sm[P_B1 + lane*4 + 3]);
    ull ab0 = pk2(sm[P_B3 + lane*4],     sm[P_B3 + lane*4 + 1]);
    ull ab1 = pk2(sm[P_B3 + lane*4 + 2], sm[P_B3 + lane*4 + 3]);

    int ngroups = (N + PNPW - 1) / PNPW;
    int gwarp = blockIdx.x * PWARPS + warp;
    int nwarp = gridDim.x * PWARPS;

    for (int g = gwarp; g < ngroups; g += nwarp) {
        int base = g * PNPW;
        #pragma unroll
        for (int u = 0; u < PNPW; u++) {
            int n = base + u;
            if (lane < 16) {
                const float4* xn = (const float4*)(x + (size_t)(n < N ? n : 0) * 64);
                float4 a = (n < N) ? xn[lane] : make_float4(0.f, 0.f, 0.f, 0.f);
                ((float4*)(buf + u * 64))[lane] = a;
            }
        }
        __syncwarp();

        ull aU0[PNPW], aU1[PNPW], aV0[PNPW], aV1[PNPW], aA0[PNPW], aA1[PNPW];
        #pragma unroll
        for (int u = 0; u < PNPW; u++) {
            aU0[u] = ub0; aU1[u] = ub1; aV0[u] = 0; aV1[u] = 0; aA0[u] = ab0; aA1[u] = ab1;
        }

        #pragma unroll 2
        for (int k = 0; k < 64; k += 2) {
            float4 uA = *(const float4*)(wup + k * 128);
            float4 uB = *(const float4*)(wup + (k + 1) * 128);
            float4 vA = *(const float4*)(wvp + k * 128);
            float4 vB = *(const float4*)(wvp + (k + 1) * 128);
            float4 wA = *(const float4*)(wap + k * 128);
            float4 wB = *(const float4*)(wap + (k + 1) * 128);
            ull uA01 = pk2(uA.x, uA.y), uA23 = pk2(uA.z, uA.w);
            ull uB01 = pk2(uB.x, uB.y), uB23 = pk2(uB.z, uB.w);
            ull vA01 = pk2(vA.x, vA.y), vA23 = pk2(vA.z, vA.w);
            ull vB01 = pk2(vB.x, vB.y), vB23 = pk2(vB.z, vB.w);
            ull wA01 = pk2(wA.x, wA.y), wA23 = pk2(wA.z, wA.w);
            ull wB01 = pk2(wB.x, wB.y), wB23 = pk2(wB.z, wB.w);
            #pragma unroll
            for (int u = 0; u < PNPW; u++) {
                float2 xv = *(const float2*)(buf + u * 64 + k);
                ull x0 = pk2(xv.x, xv.x);
                ull x1 = pk2(xv.y, xv.y);
                aU0[u] = ffma2(uA01, x0, aU0[u]);
                aU1[u] = ffma2(uA23, x0, aU1[u]);
                aV0[u] = ffma2(vA01, x0, aV0[u]);
                aV1[u] = ffma2(vA23, x0, aV1[u]);
                aA0[u] = ffma2(wA01, x0, aA0[u]);
                aA1[u] = ffma2(wA23, x0, aA1[u]);
                aU0[u] = ffma2(uB01, x1, aU0[u]);
                aU1[u] = ffma2(uB23, x1, aU1[u]);
                aV0[u] = ffma2(vB01, x1, aV0[u]);
                aV1[u] = ffma2(vB23, x1, aV1[u]);
                aA0[u] = ffma2(wB01, x1, aA0[u]);
                aA1[u] = ffma2(wB23, x1, aA1[u]);
            }
        }
        #pragma unroll
        for (int u = 0; u < PNPW; u++) {
            int n = base + u;
            if (n < N) {
                float2 p, q;
                p = upk2(aU0[u]); q = upk2(aU1[u]);
                *(float4*)(g_u + (size_t)n * 128 + lane * 4) = make_float4(p.x, p.y, q.x, q.y);
                p = upk2(aV0[u]); q = upk2(aV1[u]);
                *(float4*)(g_v + (size_t)n * 128 + lane * 4) = make_float4(p.x, p.y, q.x, q.y);
                p = upk2(aA0[u]); q = upk2(aA1[u]);
                *(float4*)(g_a + (size_t)n * 128 + lane * 4) = make_float4(p.x, p.y, q.x, q.y);
            }
        }
        __syncwarp();
    }
}

// ---------------------------- edge kernel (no GEMM) ------------------------
#define EPW 4
#define EWARPS 8
#define ETHREADS 256
#define E_SMEMF 384        // 3*128 rel-pos weight rows only
#define E_SMEMB (E_SMEMF * 4)

__global__ __launch_bounds__(ETHREADS)
void edge_kernel(const float* __restrict__ pos,
                 const int* __restrict__ idxI, const int* __restrict__ idxJ,
                 const float* __restrict__ W1, int E) {
    extern __shared__ float sm[];
    int tid = threadIdx.x;
    for (int t = tid; t < 384; t += ETHREADS) sm[t] = W1[128 * 128 + t];
    __syncthreads();

    int warp = tid >> 5, lane = tid & 31;
    float4 wp0 = *(const float4*)(sm + 0 * 128 + lane * 4);
    float4 wp1 = *(const float4*)(sm + 1 * 128 + lane * 4);
    float4 wp2 = *(const float4*)(sm + 2 * 128 + lane * 4);

    int ngroups = (E + EPW - 1) / EPW;
    int gwarp = blockIdx.x * EWARPS + warp;
    int nwarp = gridDim.x * EWARPS;

    for (int g = gwarp; g < ngroups; g += nwarp) {
        int base = g * EPW;

        // batch index loads (all LDGs in flight together)
        int ii[EPW], jj[EPW];
        #pragma unroll
        for (int e = 0; e < EPW; e++) {
            int ei = base + e;
            bool ok = ei < E;
            ii[e] = ok ? idxI[ei] : -1;
            jj[e] = ok ? idxJ[ei] : 0;
        }

        // batch U/V/pos gathers
        float4 uu[EPW], vv[EPW];
        float p0v[EPW], p1v[EPW], p2v[EPW];
        #pragma unroll
        for (int e = 0; e < EPW; e++) {
            int i = (ii[e] >= 0) ? ii[e] : 0;
            int j = jj[e];
            uu[e] = *(const float4*)(g_u + (size_t)i * 128 + lane * 4);
            vv[e] = *(const float4*)(g_v + (size_t)j * 128 + lane * 4);
            p0v[e] = pos[(size_t)j*3 + 0] - pos[(size_t)i*3 + 0];
            p1v[e] = pos[(size_t)j*3 + 1] - pos[(size_t)i*3 + 1];
            p2v[e] = pos[(size_t)j*3 + 2] - pos[(size_t)i*3 + 2];
        }

        // h = relu(U+V+rp@W1p), scatter-add 128-dim hidden + cnt
        #pragma unroll
        for (int e = 0; e < EPW; e++) {
            int i = ii[e];
            if (i >= 0) {
                float hx = fmaxf(uu[e].x + vv[e].x + p0v[e]*wp0.x + p1v[e]*wp1.x + p2v[e]*wp2.x, 0.f);
                float hy = fmaxf(uu[e].y + vv[e].y + p0v[e]*wp0.y + p1v[e]*wp1.y + p2v[e]*wp2.y, 0.f);
                float hz = fmaxf(uu[e].z + vv[e].z + p0v[e]*wp0.z + p1v[e]*wp1.z + p2v[e]*wp2.z, 0.f);
                float hw = fmaxf(uu[e].w + vv[e].w + p0v[e]*wp0.w + p1v[e]*wp1.w + p2v[e]*wp2.w, 0.f);
                float* dst = g_aggr + (size_t)i * 128 + lane * 4;
                atomicAdd(dst + 0, hx);
                atomicAdd(dst + 1, hy);
                atomicAdd(dst + 2, hz);
                atomicAdd(dst + 3, hw);
                if (lane == 0) atomicAdd(g_cnt + i, 1.0f);
            }
        }
    }
}

// ---------------------------- node kernel ----------------------------------
#define NPW 8
#define NWARPS 16
#define NTHREADS 512
#define N_W23  0
#define N_CB   16384
#define N_W4   16512
#define N_B4   24704
#define N_BUF  24768
#define N_SMEMF 41152
#define N_SMEMB (N_SMEMF * 4)

__global__ __launch_bounds__(NTHREADS, 1)
void node_kernel(const float* __restrict__ W4, const float* __restrict__ b4,
                 float* __restrict__ out, int N) {
    extern __shared__ float sm[];
    int tid = threadIdx.x;
    {
        float4* d = (float4*)(sm + N_W23); const float4* s = (const float4*)g_w23;
        for (int t = tid; t < 4096; t += NTHREADS) d[t] = s[t];
        float4* d1 = (float4*)(sm + N_CB); const float4* s1 = (const float4*)g_cb;
        for (int t = tid; t < 32; t += NTHREADS) d1[t] = s1[t];
        float4* d2 = (float4*)(sm + N_W4); const float4* s2 = (const float4*)W4;
        for (int t = tid; t < 2048; t += NTHREADS) d2[t] = s2[t];
        float4* d3 = (float4*)(sm + N_B4); const float4* s3 = (const float4*)b4;
        for (int t = tid; t < 16; t += NTHREADS) d3[t] = s3[t];
    }
    __syncthreads();

    int warp = tid >> 5, lane = tid & 31;
    float* buf = sm + N_BUF + warp * (NPW * 128);
    const float* w3p = sm + N_W23 + lane*4;
    const float* w4p = sm + N_W4 + lane*2;
    float4 cb4 = *(const float4*)(sm + N_CB + lane * 4);
    ull ob = pk2(sm[N_B4 + lane*2], sm[N_B4 + lane*2 + 1]);

    int ngroups = (N + NPW - 1) / NPW;
    int gwarp = blockIdx.x * NWARPS + warp;
    int nwarp = gridDim.x * NWARPS;

    for (int g = gwarp; g < ngroups; g += nwarp) {
        int base = g * NPW;

        float flg[NPW];
        #pragma unroll
        for (int u = 0; u < NPW; u++) {
            int n = base + u;
            if (n < N) {
                float c = g_cnt[n];
                flg[u] = (c > 0.f) ? 1.0f : 0.0f;
                float inv = 1.0f / fmaxf(c, 1.0f);
                const float4* an = (const float4*)(g_aggr + (size_t)n * 128);
                float4 b = an[lane];
                ((float4*)(buf + u * 128))[lane] =
                    make_float4(b.x*inv, b.y*inv, b.z*inv, b.w*inv);
            } else {
                flg[u] = 0.f;
                ((float4*)(buf + u * 128))[lane] = make_float4(0.f, 0.f, 0.f, 0.f);
            }
        }
        __syncwarp();

        // phase 1: meanh @ W23
        ull a0[NPW], a1[NPW];
        #pragma unroll
        for (int u = 0; u < NPW; u++) { a0[u] = 0; a1[u] = 0; }
        #pragma unroll 2
        for (int k = 0; k < 128; k += 2) {
            float4 wA = *(const float4*)(w3p + k * 128);
            float4 wB = *(const float4*)(w3p + (k + 1) * 128);
            ull wA01 = pk2(wA.x, wA.y), wA23 = pk2(wA.z, wA.w);
            ull wB01 = pk2(wB.x, wB.y), wB23 = pk2(wB.z, wB.w);
            #pragma unroll
            for (int u = 0; u < NPW; u++) {
                float2 v = *(const float2*)(buf + u*128 + k);
                ull v0 = pk2(v.x, v.x);
                ull v1 = pk2(v.y, v.y);
                a0[u] = ffma2(wA01, v0, a0[u]);
                a1[u] = ffma2(wA23, v0, a1[u]);
                a0[u] = ffma2(wB01, v1, a0[u]);
                a1[u] = ffma2(wB23, v1, a1[u]);
            }
        }
        __syncwarp();

        // epilogue: + A[n] + flag*cb, relu -> buf
        float4 A4[NPW];
        #pragma unroll
        for (int u = 0; u < NPW; u++) {
            int n = base + u;
            A4[u] = *(const float4*)(g_a + (size_t)(n < N ? n : 0) * 128 + lane * 4);
        }
        #pragma unroll
        for (int u = 0; u < NPW; u++) {
            float2 p = upk2(a0[u]);
            float2 q = upk2(a1[u]);
            float f = flg[u];
            *(float4*)(buf + u*128 + lane*4) = make_float4(
                fmaxf(p.x + A4[u].x + f*cb4.x, 0.f),
                fmaxf(p.y + A4[u].y + f*cb4.y, 0.f),
                fmaxf(q.x + A4[u].z + f*cb4.z, 0.f),
                fmaxf(q.y + A4[u].w + f*cb4.w, 0.f));
        }
        __syncwarp();

        // phase 2: out = hupd @ W4 + b4
        ull m[NPW];
        #pragma unroll
        for (int u = 0; u < NPW; u++) m[u] = ob;
        #pragma unroll 2
        for (int k = 0; k < 128; k += 2) {
            float2 wA = *(const float2*)(w4p + k * 64);
            float2 wB = *(const float2*)(w4p + (k + 1) * 64);
            ull wAp = pk2(wA.x, wA.y);
            ull wBp = pk2(wB.x, wB.y);
            #pragma unroll
            for (int u = 0; u < NPW; u++) {
                float2 h = *(const float2*)(buf + u*128 + k);
                m[u] = ffma2(wAp, pk2(h.x, h.x), m[u]);
                m[u] = ffma2(wBp, pk2(h.y, h.y), m[u]);
            }
        }
        #pragma unroll
        for (int u = 0; u < NPW; u++) {
            int n = base + u;
            if (n < N) {
                float2 rr = upk2(m[u]);
                *(float2*)(out + (size_t)n * 64 + lane * 2) = rr;
            }
        }
        __syncwarp();
    }
}

// ---------------------------- launch ---------------------------------------
extern "C" void kernel_launch(void* const* d_in, const int* in_sizes, int n_in,
                              void* d_out, int out_size) {
    const float* x   = (const float*)d_in[0];
    const float* pos = (const float*)d_in[1];
    const int*   ei  = (const int*)d_in[2];
    const float* W1  = (const float*)d_in[3];
    const float* b1  = (const float*)d_in[4];
    const float* W2  = (const float*)d_in[5];
    const float* b2  = (const float*)d_in[6];
    const float* W3  = (const float*)d_in[7];
    const float* b3  = (const float*)d_in[8];
    const float* W4  = (const float*)d_in[9];
    const float* b4  = (const float*)d_in[10];
    int N = in_sizes[0] / 64;
    int E = in_sizes[2] / 2;

    cudaFuncSetAttribute(pre_kernel,  cudaFuncAttributeMaxDynamicSharedMemorySize, P_SMEMB);
    cudaFuncSetAttribute(edge_kernel, cudaFuncAttributeMaxDynamicSharedMemorySize, E_SMEMB);
    cudaFuncSetAttribute(node_kernel, cudaFuncAttributeMaxDynamicSharedMemorySize, N_SMEMB);

    zero_kernel<<<512, 256>>>(N * 32, N);
    w23_kernel<<<129, 128>>>(W2, b2, W3);
    pre_kernel<<<304, PTHREADS, P_SMEMB>>>(x, W1, b1, W3, b3, N);
    edge_kernel<<<1216, ETHREADS, E_SMEMB>>>(pos, ei, ei + E, W1, E);
    node_kernel<<<304, NTHREADS, N_SMEMB>>>(W4, b4, (float*)d_out, N);
}

// round 17
// speedup vs baseline: 2.0522x; 1.2929x over previous
#include <cuda_runtime.h>
#include <cstdint>

// ---------------------------------------------------------------------------
// MPNN layer, fully hoisted + ATOMIC-FREE aggregation via counting sort,
// expressed in proven-construct vocabulary ONLY (float atomics, <=512-thr CTAs):
//   K0: zero cnt
//   Kw23: W23 = W2 @ W3[64:128], cb = b2 @ W3[64:128]
//   Khist: cnt[i] += 1.0 per edge (float atomics, exact)
//   Kprefix: 256-thr scan -> g_off (int), g_curf (float running slots)
//   Kscatter: slot = (int)atomicAdd(curf[i],1.0); g_sj[slot]=j
//   Kpre: U = x@(W1a-W1b)+b1, V = x@W1b, A = x@W3[0:64]+b3
//   Kagg: warp-per-node segment reduce: sum relu(U[n]+V[j]+relpos@W1p)
//         -> plain stores, ZERO float atomics in the hot path
//   Knode: meanh = aggr/max(cnt,1); relu(meanh@W23 + A + flag*cb) @ W4 + b4
// ---------------------------------------------------------------------------

#define MAXN 65536
#define MAXE 1048576
__device__ float g_aggr[MAXN * 128];
__device__ float g_cnt[MAXN];
__device__ float g_curf[MAXN];
__device__ int   g_off[MAXN];
__device__ int   g_sj[MAXE];
__device__ float g_u[MAXN * 128];
__device__ float g_v[MAXN * 128];
__device__ float g_a[MAXN * 128];
__device__ float g_w23[128 * 128];
__device__ float g_cb[128];

typedef unsigned long long ull;

__device__ __forceinline__ ull pk2(float a, float b) {
    ull r; asm("mov.b64 %0, {%1, %2};" : "=l"(r) : "f"(a), "f"(b)); return r;
}
__device__ __forceinline__ float2 upk2(ull v) {
    float2 r; asm("mov.b64 {%0, %1}, %2;" : "=f"(r.x), "=f"(r.y) : "l"(v)); return r;
}
__device__ __forceinline__ ull ffma2(ull a, ull b, ull c) {
    ull d; asm("fma.rn.f32x2 %0, %1, %2, %3;" : "=l"(d) : "l"(a), "l"(b), "l"(c)); return d;
}

// ---------------------------- zero cnt -------------------------------------
__global__ void zero_kernel(int n) {
    int stride = gridDim.x * blockDim.x;
    int t0 = blockIdx.x * blockDim.x + threadIdx.x;
    for (int i = t0; i < n; i += stride) g_cnt[i] = 0.f;
}

// ---------------------------- W23 = W2 @ W3a, cb = b2 @ W3a ----------------
__global__ void w23_kernel(const float* __restrict__ W2, const float* __restrict__ b2,
                           const float* __restrict__ W3) {
    int c = threadIdx.x;
    int k = blockIdx.x;
    float s = 0.f;
    if (k < 128) {
        #pragma unroll 8
        for (int m = 0; m < 64; m++) s += W2[k * 64 + m] * W3[(64 + m) * 128 + c];
        g_w23[k * 128 + c] = s;
    } else {
        #pragma unroll 8
        for (int m = 0; m < 64; m++) s += b2[m] * W3[(64 + m) * 128 + c];
        g_cb[c] = s;
    }
}

// ---------------------------- sorting passes (float atomics only) ----------
__global__ void hist_kernel(const int* __restrict__ idxI, int E) {
    int stride = gridDim.x * blockDim.x;
    for (int e = blockIdx.x * blockDim.x + threadIdx.x; e < E; e += stride)
        atomicAdd(&g_cnt[idxI[e]], 1.0f);
}

__global__ void prefix_kernel(int N) {
    __shared__ int part[256];
    int t = threadIdx.x;
    int C = (N + 255) / 256;
    int s0 = t * C;
    int s1 = (s0 + C < N) ? s0 + C : N;
    int sum = 0;
    for (int i = s0; i < s1; i++) sum += (int)g_cnt[i];
    part[t] = sum;
    __syncthreads();
    for (int d = 1; d < 256; d <<= 1) {
        int v = (t >= d) ? part[t - d] : 0;
        __syncthreads();
        part[t] += v;
        __syncthreads();
    }
    int run = (t == 0) ? 0 : part[t - 1];
    for (int i = s0; i < s1; i++) {
        g_off[i] = run;
        g_curf[i] = (float)run;
        run += (int)g_cnt[i];
    }
}

__global__ void scatter_kernel(const int* __restrict__ idxI, const int* __restrict__ idxJ,
                               int E) {
    int stride = gridDim.x * blockDim.x;
    for (int e = blockIdx.x * blockDim.x + threadIdx.x; e < E; e += stride) {
        int i = idxI[e];
        float old = atomicAdd(&g_curf[i], 1.0f);
        g_sj[(int)old] = idxJ[e];
    }
}

// ---------------------------- precompute U, V, A (proven) ------------------
#define PNPW 2
#define PWARPS 16
#define PTHREADS 512
#define P_WU  0
#define P_WV  8192
#define P_WA  16384
#define P_B1  24576
#define P_B3  24704
#define P_BUF 24832
#define P_SMEMF 26880
#define P_SMEMB (P_SMEMF * 4)

__global__ __launch_bounds__(PTHREADS, 1)
void pre_kernel(const float* __restrict__ x, const float* __restrict__ W1,
                const float* __restrict__ b1, const float* __restrict__ W3,
                const float* __restrict__ b3, int N) {
    extern __shared__ float sm[];
    int tid = threadIdx.x;
    for (int idx = tid; idx < 64 * 128; idx += PTHREADS) {
        float a = W1[idx];
        float b = W1[idx + 64 * 128];
        sm[P_WU + idx] = a - b;
        sm[P_WV + idx] = b;
        sm[P_WA + idx] = W3[idx];
    }
    for (int t = tid; t < 128; t += PTHREADS) { sm[P_B1 + t] = b1[t]; sm[P_B3 + t] = b3[t]; }
    __syncthreads();

    int warp = tid >> 5, lane = tid & 31;
    float* buf = sm + P_BUF + warp * (PNPW * 64);
    const float* wup = sm + P_WU + lane * 4;
    const float* wvp = sm + P_WV + lane * 4;
    const float* wap = sm + P_WA + lane * 4;

    ull ub0 = pk2(sm[P_B1 + lane*4],     sm[P_B1 + lane*4 + 1]);
    ull ub1 = pk2(sm[P_B1 + lane*4 + 2], sm[P_B1 + lane*4 + 3]);
    ull ab0 = pk2(sm[P_B3 + lane*4],     sm[P_B3 + lane*4 + 1]);
    ull ab1 = pk2(sm[P_B3 + lane*4 + 2], sm[P_B3 + lane*4 + 3]);

    int ngroups = (N + PNPW - 1) / PNPW;
    int gwarp = blockIdx.x * PWARPS + warp;
    int nwarp = gridDim.x * PWARPS;

    for (int g = gwarp; g < ngroups; g += nwarp) {
        int base = g * PNPW;
        #pragma unroll
        for (int u = 0; u < PNPW; u++) {
            int n = base + u;
            if (lane < 16) {
                const float4* xn = (const float4*)(x + (size_t)(n < N ? n : 0) * 64);
                float4 a = (n < N) ? xn[lane] : make_float4(0.f, 0.f, 0.f, 0.f);
                ((float4*)(buf + u * 64))[lane] = a;
            }
        }
        __syncwarp();

        ull aU0[PNPW], aU1[PNPW], aV0[PNPW], aV1[PNPW], aA0[PNPW], aA1[PNPW];
        #pragma unroll
        for (int u = 0; u < PNPW; u++) {
            aU0[u] = ub0; aU1[u] = ub1; aV0[u] = 0; aV1[u] = 0; aA0[u] = ab0; aA1[u] = ab1;
        }

        #pragma unroll 2
        for (int k = 0; k < 64; k += 2) {
            float4 uA = *(const float4*)(wup + k * 128);
            float4 uB = *(const float4*)(wup + (k + 1) * 128);
            float4 vA = *(const float4*)(wvp + k * 128);
            float4 vB = *(const float4*)(wvp + (k + 1) * 128);
            float4 wA = *(const float4*)(wap + k * 128);
            float4 wB = *(const float4*)(wap + (k + 1) * 128);
            ull uA01 = pk2(uA.x, uA.y), uA23 = pk2(uA.z, uA.w);
            ull uB01 = pk2(uB.x, uB.y), uB23 = pk2(uB.z, uB.w);
            ull vA01 = pk2(vA.x, vA.y), vA23 = pk2(vA.z, vA.w);
            ull vB01 = pk2(vB.x, vB.y), vB23 = pk2(vB.z, vB.w);
            ull wA01 = pk2(wA.x, wA.y), wA23 = pk2(wA.z, wA.w);
            ull wB01 = pk2(wB.x, wB.y), wB23 = pk2(wB.z, wB.w);
            #pragma unroll
            for (int u = 0; u < PNPW; u++) {
                float2 xv = *(const float2*)(buf + u * 64 + k);
                ull x0 = pk2(xv.x, xv.x);
                ull x1 = pk2(xv.y, xv.y);
                aU0[u] = ffma2(uA01, x0, aU0[u]);
                aU1[u] = ffma2(uA23, x0, aU1[u]);
                aV0[u] = ffma2(vA01, x0, aV0[u]);
                aV1[u] = ffma2(vA23, x0, aV1[u]);
                aA0[u] = ffma2(wA01, x0, aA0[u]);
                aA1[u] = ffma2(wA23, x0, aA1[u]);
                aU0[u] = ffma2(uB01, x1, aU0[u]);
                aU1[u] = ffma2(uB23, x1, aU1[u]);
                aV0[u] = ffma2(vB01, x1, aV0[u]);
                aV1[u] = ffma2(vB23, x1, aV1[u]);
                aA0[u] = ffma2(wB01, x1, aA0[u]);
                aA1[u] = ffma2(wB23, x1, aA1[u]);
            }
        }
        #pragma unroll
        for (int u = 0; u < PNPW; u++) {
            int n = base + u;
            if (n < N) {
                float2 p, q;
                p = upk2(aU0[u]); q = upk2(aU1[u]);
                *(float4*)(g_u + (size_t)n * 128 + lane * 4) = make_float4(p.x, p.y, q.x, q.y);
                p = upk2(aV0[u]); q = upk2(aV1[u]);
                *(float4*)(g_v + (size_t)n * 128 + lane * 4) = make_float4(p.x, p.y, q.x, q.y);
                p = upk2(aA0[u]); q = upk2(aA1[u]);
                *(float4*)(g_a + (size_t)n * 128 + lane * 4) = make_float4(p.x, p.y, q.x, q.y);
            }
        }
        __syncwarp();
    }
}

// ---------------------------- warp-per-node aggregate (no atomics) ---------
#define AWARPS 8
#define ATHREADS 256
#define A_SMEMF 384
#define A_SMEMB (A_SMEMF * 4)

__global__ __launch_bounds__(ATHREADS)
void agg_kernel(const float* __restrict__ pos, const float* __restrict__ W1, int N) {
    extern __shared__ float sm[];
    int tid = threadIdx.x;
    for (int t = tid; t < 384; t += ATHREADS) sm[t] = W1[128 * 128 + t];
    __syncthreads();

    int warp = tid >> 5, lane = tid & 31;
    float4 wp0 = *(const float4*)(sm + 0 * 128 + lane * 4);
    float4 wp1 = *(const float4*)(sm + 1 * 128 + lane * 4);
    float4 wp2 = *(const float4*)(sm + 2 * 128 + lane * 4);

    int gwarp = blockIdx.x * AWARPS + warp;
    int nwarp = gridDim.x * AWARPS;

    for (int n = gwarp; n < N; n += nwarp) {
        int s = g_off[n];
        int cnt = (int)g_cnt[n];
        float4 u = *(const float4*)(g_u + (size_t)n * 128 + lane * 4);
        float pi0 = pos[(size_t)n*3 + 0];
        float pi1 = pos[(size_t)n*3 + 1];
        float pi2 = pos[(size_t)n*3 + 2];
        float4 acc = make_float4(0.f, 0.f, 0.f, 0.f);

        int e = s;
        int eend = s + cnt;
        for (; e + 2 <= eend; e += 2) {
            int j0 = g_sj[e], j1 = g_sj[e + 1];
            float4 v0 = *(const float4*)(g_v + (size_t)j0 * 128 + lane * 4);
            float4 v1 = *(const float4*)(g_v + (size_t)j1 * 128 + lane * 4);
            float q00 = pos[(size_t)j0*3 + 0] - pi0;
            float q01 = pos[(size_t)j0*3 + 1] - pi1;
            float q02 = pos[(size_t)j0*3 + 2] - pi2;
            float q10 = pos[(size_t)j1*3 + 0] - pi0;
            float q11 = pos[(size_t)j1*3 + 1] - pi1;
            float q12 = pos[(size_t)j1*3 + 2] - pi2;
            acc.x += fmaxf(u.x + v0.x + q00*wp0.x + q01*wp1.x + q02*wp2.x, 0.f)
                   + fmaxf(u.x + v1.x + q10*wp0.x + q11*wp1.x + q12*wp2.x, 0.f);
            acc.y += fmaxf(u.y + v0.y + q00*wp0.y + q01*wp1.y + q02*wp2.y, 0.f)
                   + fmaxf(u.y + v1.y + q10*wp0.y + q11*wp1.y + q12*wp2.y, 0.f);
            acc.z += fmaxf(u.z + v0.z + q00*wp0.z + q01*wp1.z + q02*wp2.z, 0.f)
                   + fmaxf(u.z + v1.z + q10*wp0.z + q11*wp1.z + q12*wp2.z, 0.f);
            acc.w += fmaxf(u.w + v0.w + q00*wp0.w + q01*wp1.w + q02*wp2.w, 0.f)
                   + fmaxf(u.w + v1.w + q10*wp0.w + q11*wp1.w + q12*wp2.w, 0.f);
        }
        if (e < eend) {
            int j0 = g_sj[e];
            float4 v0 = *(const float4*)(g_v + (size_t)j0 * 128 + lane * 4);
            float q00 = pos[(size_t)j0*3 + 0] - pi0;
            float q01 = pos[(size_t)j0*3 + 1] - pi1;
            float q02 = pos[(size_t)j0*3 + 2] - pi2;
            acc.x += fmaxf(u.x + v0.x + q00*wp0.x + q01*wp1.x + q02*wp2.x, 0.f);
            acc.y += fmaxf(u.y + v0.y + q00*wp0.y + q01*wp1.y + q02*wp2.y, 0.f);
            acc.z += fmaxf(u.z + v0.z + q00*wp0.z + q01*wp1.z + q02*wp2.z, 0.f);
            acc.w += fmaxf(u.w + v0.w + q00*wp0.w + q01*wp1.w + q02*wp2.w, 0.f);
        }

        *(float4*)(g_aggr + (size_t)n * 128 + lane * 4) = acc;
    }
}

// ---------------------------- node kernel (proven) -------------------------
#define NPW 8
#define NWARPS 16
#define NTHREADS 512
#define N_W23  0
#define N_CB   16384
#define N_W4   16512
#define N_B4   24704
#define N_BUF  24768
#define N_SMEMF 41152
#define N_SMEMB (N_SMEMF * 4)

__global__ __launch_bounds__(NTHREADS, 1)
void node_kernel(const float* __restrict__ W4, const float* __restrict__ b4,
                 float* __restrict__ out, int N) {
    extern __shared__ float sm[];
    int tid = threadIdx.x;
    {
        float4* d = (float4*)(sm + N_W23); const float4* s = (const float4*)g_w23;
        for (int t = tid; t < 4096; t += NTHREADS) d[t] = s[t];
        float4* d1 = (float4*)(sm + N_CB); const float4* s1 = (const float4*)g_cb;
        for (int t = tid; t < 32; t += NTHREADS) d1[t] = s1[t];
        float4* d2 = (float4*)(sm + N_W4); const float4* s2 = (const float4*)W4;
        for (int t = tid; t < 2048; t += NTHREADS) d2[t] = s2[t];
        float4* d3 = (float4*)(sm + N_B4); const float4* s3 = (const float4*)b4;
        for (int t = tid; t < 16; t += NTHREADS) d3[t] = s3[t];
    }
    __syncthreads();

    int warp = tid >> 5, lane = tid & 31;
    float* buf = sm + N_BUF + warp * (NPW * 128);
    const float* w3p = sm + N_W23 + lane*4;
    const float* w4p = sm + N_W4 + lane*2;
    float4 cb4 = *(const float4*)(sm + N_CB + lane * 4);
    ull ob = pk2(sm[N_B4 + lane*2], sm[N_B4 + lane*2 + 1]);

    int ngroups = (N + NPW - 1) / NPW;
    int gwarp = blockIdx.x * NWARPS + warp;
    int nwarp = gridDim.x * NWARPS;

    for (int g = gwarp; g < ngroups; g += nwarp) {
        int base = g * NPW;

        float flg[NPW];
        #pragma unroll
        for (int u = 0; u < NPW; u++) {
            int n = base + u;
            if (n < N) {
                float c = g_cnt[n];
                flg[u] = (c > 0.f) ? 1.0f : 0.0f;
                float inv = 1.0f / fmaxf(c, 1.0f);
                const float4* an = (const float4*)(g_aggr + (size_t)n * 128);
                float4 b = an[lane];
                ((float4*)(buf + u * 128))[lane] =
                    make_float4(b.x*inv, b.y*inv, b.z*inv, b.w*inv);
            } else {
                flg[u] = 0.f;
                ((float4*)(buf + u * 128))[lane] = make_float4(0.f, 0.f, 0.f, 0.f);
            }
        }
        __syncwarp();

        // phase 1: meanh @ W23
        ull a0[NPW], a1[NPW];
        #pragma unroll
        for (int u = 0; u < NPW; u++) { a0[u] = 0; a1[u] = 0; }
        #pragma unroll 2
        for (int k = 0; k < 128; k += 2) {
            float4 wA = *(const float4*)(w3p + k * 128);
            float4 wB = *(const float4*)(w3p + (k + 1) * 128);
            ull wA01 = pk2(wA.x, wA.y), wA23 = pk2(wA.z, wA.w);
            ull wB01 = pk2(wB.x, wB.y), wB23 = pk2(wB.z, wB.w);
            #pragma unroll
            for (int u = 0; u < NPW; u++) {
                float2 v = *(const float2*)(buf + u*128 + k);
                ull v0 = pk2(v.x, v.x);
                ull v1 = pk2(v.y, v.y);
                a0[u] = ffma2(wA01, v0, a0[u]);
                a1[u] = ffma2(wA23, v0, a1[u]);
                a0[u] = ffma2(wB01, v1, a0[u]);
                a1[u] = ffma2(wB23, v1, a1[u]);
            }
        }
        __syncwarp();

        // epilogue: + A[n] + flag*cb, relu -> buf
        float4 A4[NPW];
        #pragma unroll
        for (int u = 0; u < NPW; u++) {
            int n = base + u;
            A4[u] = *(const float4*)(g_a + (size_t)(n < N ? n : 0) * 128 + lane * 4);
        }
        #pragma unroll
        for (int u = 0; u < NPW; u++) {
            float2 p = upk2(a0[u]);
            float2 q = upk2(a1[u]);
            float f = flg[u];
            *(float4*)(buf + u*128 + lane*4) = make_float4(
                fmaxf(p.x + A4[u].x + f*cb4.x, 0.f),
                fmaxf(p.y + A4[u].y + f*cb4.y, 0.f),
                fmaxf(q.x + A4[u].z + f*cb4.z, 0.f),
                fmaxf(q.y + A4[u].w + f*cb4.w, 0.f));
        }
        __syncwarp();

        // phase 2: out = hupd @ W4 + b4
        ull m[NPW];
        #pragma unroll
        for (int u = 0; u < NPW; u++) m[u] = ob;
        #pragma unroll 2
        for (int k = 0; k < 128; k += 2) {
            float2 wA = *(const float2*)(w4p + k * 64);
            float2 wB = *(const float2*)(w4p + (k + 1) * 64);
            ull wAp = pk2(wA.x, wA.y);
            ull wBp = pk2(wB.x, wB.y);
            #pragma unroll
            for (int u = 0; u < NPW; u++) {
                float2 h = *(const float2*)(buf + u*128 + k);
                m[u] = ffma2(wAp, pk2(h.x, h.x), m[u]);
                m[u] = ffma2(wBp, pk2(h.y, h.y), m[u]);
            }
        }
        #pragma unroll
        for (int u = 0; u < NPW; u++) {
            int n = base + u;
            if (n < N) {
                float2 rr = upk2(m[u]);
                *(float2*)(out + (size_t)n * 64 + lane * 2) = rr;
            }
        }
        __syncwarp();
    }
}

// ---------------------------- launch ---------------------------------------
extern "C" void kernel_launch(void* const* d_in, const int* in_sizes, int n_in,
                              void* d_out, int out_size) {
    const float* x   = (const float*)d_in[0];
    const float* pos = (const float*)d_in[1];
    const int*   ei  = (const int*)d_in[2];
    const float* W1  = (const float*)d_in[3];
    const float* b1  = (const float*)d_in[4];
    const float* W2  = (const float*)d_in[5];
    const float* b2  = (const float*)d_in[6];
    const float* W3  = (const float*)d_in[7];
    const float* b3  = (const float*)d_in[8];
    const float* W4  = (const float*)d_in[9];
    const float* b4  = (const float*)d_in[10];
    int N = in_sizes[0] / 64;
    int E = in_sizes[2] / 2;

    cudaFuncSetAttribute(pre_kernel,  cudaFuncAttributeMaxDynamicSharedMemorySize, P_SMEMB);
    cudaFuncSetAttribute(agg_kernel,  cudaFuncAttributeMaxDynamicSharedMemorySize, A_SMEMB);
    cudaFuncSetAttribute(node_kernel, cudaFuncAttributeMaxDynamicSharedMemorySize, N_SMEMB);

    zero_kernel<<<128, 256>>>(N);
    w23_kernel<<<129, 128>>>(W2, b2, W3);
    hist_kernel<<<512, 256>>>(ei, E);
    prefix_kernel<<<1, 256>>>(N);
    scatter_kernel<<<512, 256>>>(ei, ei + E, E);
    pre_kernel<<<304, PTHREADS, P_SMEMB>>>(x, W1, b1, W3, b3, N);
    agg_kernel<<<1024, ATHREADS, A_SMEMB>>>(pos, W1, N);
    node_kernel<<<304, NTHREADS, N_SMEMB>>>(W4, b4, (float*)d_out, N);
}